// round 13
// baseline (speedup 1.0000x reference)
#include <cuda_runtime.h>
#include <cuda_fp16.h>
#include <stdint.h>

#define NMAX 100000
#define EMAX 1600000

// ---------------- scratch (static device globals) ----------------
__device__ __align__(16) float  g_q  [(size_t)NMAX * 128];
// interleaved kv: per node 256 halves = [k0..3 | v0..3 | k4..7 | v4..7 | ...]
__device__ __align__(16) __half g_kv [(size_t)NMAX * 256];
__device__ __align__(16) float  g_agg[(size_t)NMAX * 128];
__device__ __align__(16) float  g_h  [(size_t)NMAX * 128];
__device__ __align__(16) float  g_hn [(size_t)NMAX * 128];
__device__ __align__(16) float  g_t2 [(size_t)NMAX * 64];
// CSR  (g_deg zeroed by scatter_kernel AFTER scan consumes it -> next replay sees zeros;
//       first call relies on module-load zero-init; deterministic across replays)
__device__ int    g_deg[NMAX];
__device__ int    g_rowptr[NMAX + 1];
__device__ int    g_cursor[NMAX];
__device__ int    g_esrc[EMAX];
__device__ __align__(8) float2 g_eea[EMAX];

__device__ __forceinline__ int clampi(int v, int hi) {
    return v < 0 ? 0 : (v >= hi ? hi - 1 : v);
}
__device__ __forceinline__ uint32_t f2tf32(float f) {
    uint32_t u;
    asm("cvt.rna.tf32.f32 %0, %1;" : "=r"(u) : "f"(f));
    return u;
}
__device__ __forceinline__ uint4 f2tf32_v4(float4 f) {
    uint4 u;
    u.x = f2tf32(f.x); u.y = f2tf32(f.y); u.z = f2tf32(f.z); u.w = f2tf32(f.w);
    return u;
}
__device__ __forceinline__ void mma_tf32(float4& c, const uint32_t a[4], const uint32_t b[2]) {
    asm("mma.sync.aligned.m16n8k8.row.col.f32.tf32.tf32.f32 "
        "{%0,%1,%2,%3}, {%4,%5,%6,%7}, {%8,%9}, {%0,%1,%2,%3};"
        : "+f"(c.x), "+f"(c.y), "+f"(c.z), "+f"(c.w)
        : "r"(a[0]), "r"(a[1]), "r"(a[2]), "r"(a[3]), "r"(b[0]), "r"(b[1]));
}

// ---------------- CSR build ----------------
__global__ void hist_kernel(const int* __restrict__ ei, int E, int n) {
    int e = blockIdx.x * blockDim.x + threadIdx.x;
    if (e < E) atomicAdd(&g_deg[clampi(ei[E + e], n)], 1);
}
__global__ __launch_bounds__(1024)
void scan_kernel(int n) {
    __shared__ int sh[1024];
    int t = threadIdx.x;
    int chunk = (n + 1023) >> 10;
    int b = t * chunk;
    int e = min(n, b + chunk);
    int s = 0;
    for (int i = b; i < e; ++i) s += g_deg[i];
    sh[t] = s;
    __syncthreads();
    for (int off = 1; off < 1024; off <<= 1) {
        int v = (t >= off) ? sh[t - off] : 0;
        __syncthreads();
        sh[t] += v;
        __syncthreads();
    }
    int base = (t == 0) ? 0 : sh[t - 1];
    for (int i = b; i < e; ++i) {
        int d = g_deg[i];
        g_rowptr[i] = base;
        g_cursor[i] = base;
        base += d;
    }
    if (t == 1023) g_rowptr[n] = sh[1023];
}
// scatter + re-zero g_deg for the next replay
__global__ void scatter_kernel(const int* __restrict__ ei, const float* __restrict__ ea,
                               int E, int n) {
    int e = blockIdx.x * blockDim.x + threadIdx.x;
    if (e < n) g_deg[e] = 0;
    if (e >= E) return;
    int src = clampi(ei[e], n);
    int dst = clampi(ei[E + e], n);
    int pos = atomicAdd(&g_cursor[dst], 1);
    g_esrc[pos] = src;
    g_eea[pos]  = *reinterpret_cast<const float2*>(ea + (size_t)e * 2);
}

// ---------------- tf32 tensor-core GEMM, K=128, M-tile=128, N-tile=NT ----------------
// Software-pipelined k-loop (register prefetch) + STS.128 staging.
// EPI 0: qkv split -> q fp32 plane + interleaved kv fp16
// EPI 1: bias + resid -> C (NCOLS=128)
// EPI 2: bias + relu  -> C (NCOLS=64, NT=64)
template<int NT, int EPI>
__global__ __launch_bounds__(256)
void gemm_tf32(const float* __restrict__ A, const float* __restrict__ B,
               const float* __restrict__ bias, const float* __restrict__ resid,
               float* __restrict__ C, __half* __restrict__ Hkv, int M, int NCOLS)
{
    constexpr int WM = (NT == 128) ? 2 : 4;
    constexpr int WN = 8 / WM;
    constexpr int MFRAG = 8 / WM;
    constexpr int NFRAG = NT / (WN * 8);
    constexpr int BJ = NT / 64;   // B float4 loads per thread per iter

    __shared__ uint32_t As[128][20];
    __shared__ uint32_t Bs[16][NT + 8];

    const int t = threadIdx.x;
    const int lane = t & 31;
    const int wid  = t >> 5;
    const int warp_m = wid / WN;
    const int warp_n = wid % WN;
    const int m0 = blockIdx.x * 128;
    const int n0 = blockIdx.y * NT;
    const int lr = lane >> 2, lc = lane & 3;

    float4 acc[MFRAG][NFRAG];
#pragma unroll
    for (int i = 0; i < MFRAG; ++i)
#pragma unroll
        for (int j = 0; j < NFRAG; ++j) acc[i][j] = make_float4(0.f, 0.f, 0.f, 0.f);

    const int arow = t >> 1;
    const int acb  = (t & 1) * 8;
    int agr = m0 + arow; if (agr >= M) agr = M - 1;
    const float* Ap = A + (size_t)agr * 128 + acb;

    const int brow = t >> 4;
    const int bcb  = (t & 15) * (NT / 16);
    const float* Bp = B + (size_t)brow * NCOLS + n0 + bcb;

    // prologue prefetch (k0 = 0)
    float4 av0 = *reinterpret_cast<const float4*>(Ap);
    float4 av1 = *reinterpret_cast<const float4*>(Ap + 4);
    float4 bv[BJ];
#pragma unroll
    for (int j = 0; j < BJ; ++j)
        bv[j] = *reinterpret_cast<const float4*>(Bp + j * 4);

    for (int k0 = 0; k0 < 128; k0 += 16) {
        // stage current regs -> smem (tf32 cvt + STS.128)
        *reinterpret_cast<uint4*>(&As[arow][acb])     = f2tf32_v4(av0);
        *reinterpret_cast<uint4*>(&As[arow][acb + 4]) = f2tf32_v4(av1);
#pragma unroll
        for (int j = 0; j < BJ; ++j)
            *reinterpret_cast<uint4*>(&Bs[brow][bcb + j * 4]) = f2tf32_v4(bv[j]);
        __syncthreads();

        // prefetch next iteration (LDG in flight during MMA compute)
        if (k0 + 16 < 128) {
            av0 = *reinterpret_cast<const float4*>(Ap + k0 + 16);
            av1 = *reinterpret_cast<const float4*>(Ap + k0 + 20);
#pragma unroll
            for (int j = 0; j < BJ; ++j)
                bv[j] = *reinterpret_cast<const float4*>(Bp + (size_t)(k0 + 16) * NCOLS + j * 4);
        }

#pragma unroll
        for (int ks = 0; ks < 16; ks += 8) {
            uint32_t afr[MFRAG][4];
#pragma unroll
            for (int fm = 0; fm < MFRAG; ++fm) {
                int mr = warp_m * (MFRAG * 16) + fm * 16 + lr;
                afr[fm][0] = As[mr][ks + lc];
                afr[fm][1] = As[mr + 8][ks + lc];
                afr[fm][2] = As[mr][ks + lc + 4];
                afr[fm][3] = As[mr + 8][ks + lc + 4];
            }
            uint32_t bfr[NFRAG][2];
#pragma unroll
            for (int fn = 0; fn < NFRAG; ++fn) {
                int nc = warp_n * (NFRAG * 8) + fn * 8 + lr;
                bfr[fn][0] = Bs[ks + lc][nc];
                bfr[fn][1] = Bs[ks + lc + 4][nc];
            }
#pragma unroll
            for (int fm = 0; fm < MFRAG; ++fm)
#pragma unroll
                for (int fn = 0; fn < NFRAG; ++fn)
                    mma_tf32(acc[fm][fn], afr[fm], bfr[fn]);
        }
        __syncthreads();
    }

    const int plane = n0 >> 7;
#pragma unroll
    for (int fm = 0; fm < MFRAG; ++fm) {
        int r0 = m0 + warp_m * (MFRAG * 16) + fm * 16 + lr;
        int r1 = r0 + 8;
#pragma unroll
        for (int fn = 0; fn < NFRAG; ++fn) {
            int cl = warp_n * (NFRAG * 8) + fn * 8 + 2 * lc;
            float4 c = acc[fm][fn];
            if (EPI == 0) {
                if (plane == 0) {
                    if (r0 < M) *reinterpret_cast<float2*>(C + (size_t)r0 * 128 + cl) = make_float2(c.x, c.y);
                    if (r1 < M) *reinterpret_cast<float2*>(C + (size_t)r1 * 128 + cl) = make_float2(c.z, c.w);
                } else {
                    int hi = ((cl >> 2) << 3) + (cl & 3) + ((plane == 2) ? 4 : 0);
                    if (r0 < M) *reinterpret_cast<__half2*>(Hkv + (size_t)r0 * 256 + hi) = __floats2half2_rn(c.x, c.y);
                    if (r1 < M) *reinterpret_cast<__half2*>(Hkv + (size_t)r1 * 256 + hi) = __floats2half2_rn(c.z, c.w);
                }
            } else {
                int col = n0 + cl;
                float b0 = bias[col], b1 = bias[col + 1];
                if (EPI == 1) {
                    if (r0 < M) {
                        float2 rr = *reinterpret_cast<const float2*>(resid + (size_t)r0 * NCOLS + col);
                        *reinterpret_cast<float2*>(C + (size_t)r0 * NCOLS + col) =
                            make_float2(c.x + b0 + rr.x, c.y + b1 + rr.y);
                    }
                    if (r1 < M) {
                        float2 rr = *reinterpret_cast<const float2*>(resid + (size_t)r1 * NCOLS + col);
                        *reinterpret_cast<float2*>(C + (size_t)r1 * NCOLS + col) =
                            make_float2(c.z + b0 + rr.x, c.w + b1 + rr.y);
                    }
                } else {
                    if (r0 < M)
                        *reinterpret_cast<float2*>(C + (size_t)r0 * NCOLS + col) =
                            make_float2(fmaxf(c.x + b0, 0.f), fmaxf(c.y + b1, 0.f));
                    if (r1 < M)
                        *reinterpret_cast<float2*>(C + (size_t)r1 * NCOLS + col) =
                            make_float2(fmaxf(c.z + b0, 0.f), fmaxf(c.w + b1, 0.f));
                }
            }
        }
    }
}

// ---------------- fused CSR attention: 1 warp/node, EPW=8, ONE LDG.128 per edge ----------------
__global__ __launch_bounds__(128)
void fused_attn(const float* __restrict__ Wedge, int n)
{
    constexpr int EPW = 8;
    int i    = (blockIdx.x * blockDim.x + threadIdx.x) >> 5;
    int lane = threadIdx.x & 31;
    if (i >= n) return;
    int hg = lane >> 2;

    int beg = g_rowptr[i];
    int end = g_rowptr[i + 1];

    float4 q4 = *reinterpret_cast<const float4*>(g_q + (size_t)i * 128 + lane * 4);
    q4.x *= 0.25f; q4.y *= 0.25f; q4.z *= 0.25f; q4.w *= 0.25f;
    float w0 = Wedge[hg], w1 = Wedge[8 + hg];

    float4 accv = {0.f, 0.f, 0.f, 0.f};
    float  accd = 0.f;

    for (int j = beg; j < end; j += EPW) {
        int   idx[EPW];
        float sb[EPW];
#pragma unroll
        for (int u = 0; u < EPW; ++u) {
            int jj = min(j + u, end - 1);
            idx[u] = __ldg(g_esrc + jj);
            float2 ea2 = g_eea[jj];
            sb[u] = ea2.x * w0 + ea2.y * w1;
        }
        uint4 kv[EPW];
#pragma unroll
        for (int u = 0; u < EPW; ++u)
            kv[u] = *reinterpret_cast<const uint4*>(g_kv + (size_t)idx[u] * 256 + lane * 8);

        float ex[EPW];
#pragma unroll
        for (int u = 0; u < EPW; ++u) {
            float2 ka = __half22float2(*reinterpret_cast<const __half2*>(&kv[u].x));
            float2 kb = __half22float2(*reinterpret_cast<const __half2*>(&kv[u].y));
            float p = q4.x * ka.x + q4.y * ka.y + q4.z * kb.x + q4.w * kb.y;
            p += __shfl_xor_sync(0xffffffffu, p, 1);
            p += __shfl_xor_sync(0xffffffffu, p, 2);
            float e = __expf(p + sb[u]);
            ex[u] = (j + u < end) ? e : 0.f;
            accd += ex[u];
        }
#pragma unroll
        for (int u = 0; u < EPW; ++u) {
            float2 va = __half22float2(*reinterpret_cast<const __half2*>(&kv[u].z));
            float2 vb = __half22float2(*reinterpret_cast<const __half2*>(&kv[u].w));
            accv.x += ex[u] * va.x;
            accv.y += ex[u] * va.y;
            accv.z += ex[u] * vb.x;
            accv.w += ex[u] * vb.y;
        }
    }

    float invd = __fdividef(1.f, accd + 1e-16f);
    float4 o = {accv.x * invd, accv.y * invd, accv.z * invd, accv.w * invd};
    *reinterpret_cast<float4*>(g_agg + (size_t)i * 128 + lane * 4) = o;
}

// ---------------- layernorm ----------------
__global__ __launch_bounds__(256)
void ln_kernel(const float* __restrict__ lw, const float* __restrict__ lb, int n)
{
    int node = (blockIdx.x * blockDim.x + threadIdx.x) >> 5;
    int lane = threadIdx.x & 31;
    if (node >= n) return;

    float4 v = *reinterpret_cast<const float4*>(g_h + (size_t)node * 128 + lane * 4);
    float s = v.x + v.y + v.z + v.w;
    float q = v.x * v.x + v.y * v.y + v.z * v.z + v.w * v.w;
#pragma unroll
    for (int o = 16; o; o >>= 1) {
        s += __shfl_xor_sync(0xffffffffu, s, o);
        q += __shfl_xor_sync(0xffffffffu, q, o);
    }
    float mu  = s * (1.f / 128.f);
    float var = q * (1.f / 128.f) - mu * mu;
    float rs  = rsqrtf(var + 1e-5f);
    float4 w4 = *reinterpret_cast<const float4*>(lw + lane * 4);
    float4 b4 = *reinterpret_cast<const float4*>(lb + lane * 4);
    float4 o;
    o.x = (v.x - mu) * rs * w4.x + b4.x;
    o.y = (v.y - mu) * rs * w4.y + b4.y;
    o.z = (v.z - mu) * rs * w4.z + b4.z;
    o.w = (v.w - mu) * rs * w4.w + b4.w;
    *reinterpret_cast<float4*>(g_hn + (size_t)node * 128 + lane * 4) = o;
}

// ---------------- final: out[N,3] = t2[N,64] @ Wc2[64,3] + bc2 ----------------
__global__ __launch_bounds__(256)
void final_kernel(const float* __restrict__ Wc2, const float* __restrict__ bc2,
                  float* __restrict__ out, int n)
{
    int node = (blockIdx.x * blockDim.x + threadIdx.x) >> 5;
    int lane = threadIdx.x & 31;
    if (node >= n) return;

    float2 tv = *reinterpret_cast<const float2*>(g_t2 + (size_t)node * 64 + lane * 2);
    int k0 = lane * 2;
    float s0 = tv.x * Wc2[k0 * 3 + 0] + tv.y * Wc2[k0 * 3 + 3];
    float s1 = tv.x * Wc2[k0 * 3 + 1] + tv.y * Wc2[k0 * 3 + 4];
    float s2 = tv.x * Wc2[k0 * 3 + 2] + tv.y * Wc2[k0 * 3 + 5];
#pragma unroll
    for (int o = 16; o; o >>= 1) {
        s0 += __shfl_xor_sync(0xffffffffu, s0, o);
        s1 += __shfl_xor_sync(0xffffffffu, s1, o);
        s2 += __shfl_xor_sync(0xffffffffu, s2, o);
    }
    if (lane == 0) {
        out[(size_t)node * 3 + 0] = s0 + bc2[0];
        out[(size_t)node * 3 + 1] = s1 + bc2[1];
        out[(size_t)node * 3 + 2] = s2 + bc2[2];
    }
}

// ---------------- launch ----------------
extern "C" void kernel_launch(void* const* d_in, const int* in_sizes, int n_in,
                              void* d_out, int out_size)
{
    const float* x     = (const float*)d_in[0];
    const int*   ei    = (const int*)d_in[1];
    const float* ea    = (const float*)d_in[2];
    const float* Wqkv  = (const float*)d_in[3];
    const float* Wedge = (const float*)d_in[4];
    const float* Wout  = (const float*)d_in[5];
    const float* bout  = (const float*)d_in[6];
    const float* lnw   = (const float*)d_in[7];
    const float* lnb   = (const float*)d_in[8];
    const float* Wc1   = (const float*)d_in[9];
    const float* bc1   = (const float*)d_in[10];
    const float* Wc2   = (const float*)d_in[11];
    const float* bc2   = (const float*)d_in[12];
    float* out = (float*)d_out;

    const int n = in_sizes[0] / 128;
    const int E = in_sizes[1] / 2;

    float *q, *agg, *h, *hn, *t2;
    __half* kv;
    cudaGetSymbolAddress((void**)&q,   g_q);
    cudaGetSymbolAddress((void**)&kv,  g_kv);
    cudaGetSymbolAddress((void**)&agg, g_agg);
    cudaGetSymbolAddress((void**)&h,   g_h);
    cudaGetSymbolAddress((void**)&hn,  g_hn);
    cudaGetSymbolAddress((void**)&t2,  g_t2);

    // 1. edge histogram (g_deg zeroed by previous scatter / module init)
    hist_kernel<<<(E + 255) / 256, 256>>>(ei, E, n);

    // 2. exclusive scan -> rowptr/cursor
    scan_kernel<<<1, 1024>>>(n);

    // 3. scatter edges into CSR (+ re-zero g_deg for next replay)
    scatter_kernel<<<(E + 255) / 256, 256>>>(ei, ea, E, n);

    // 4. qkv = x @ Wqkv -> q fp32 + interleaved kv fp16   <-- profiled slot
    gemm_tf32<128, 0><<<dim3((n + 127) / 128, 3), 256>>>(
        x, Wqkv, nullptr, nullptr, q, kv, n, 384);

    // 5. fused per-node attention
    fused_attn<<<(n + 3) / 4, 128>>>(Wedge, n);

    // 6. h = agg @ Wout + bout + x
    gemm_tf32<128, 1><<<dim3((n + 127) / 128, 1), 256>>>(
        agg, Wout, bout, x, h, nullptr, n, 128);

    // 7. layernorm
    ln_kernel<<<(n + 7) / 8, 256>>>(lnw, lnb, n);

    // 8. t2 = relu(hn @ Wc1 + bc1)
    gemm_tf32<64, 2><<<dim3((n + 127) / 128, 1), 256>>>(
        hn, Wc1, bc1, nullptr, t2, nullptr, n, 64);

    // 9. out = t2 @ Wc2 + bc2
    final_kernel<<<(n + 7) / 8, 256>>>(Wc2, bc2, out, n);
}

// round 14
// speedup vs baseline: 1.4347x; 1.4347x over previous
#include <cuda_runtime.h>
#include <cuda_fp16.h>
#include <stdint.h>

#define NMAX 100000
#define EMAX 1600000

// ---------------- scratch (static device globals) ----------------
__device__ __align__(16) float  g_q  [(size_t)NMAX * 128];
// interleaved kv: per node 256 halves = [k0..3 | v0..3 | k4..7 | v4..7 | ...]
__device__ __align__(16) __half g_kv [(size_t)NMAX * 256];
__device__ __align__(16) float  g_agg[(size_t)NMAX * 128];
__device__ __align__(16) float  g_h  [(size_t)NMAX * 128];
__device__ __align__(16) float  g_hn [(size_t)NMAX * 128];
__device__ __align__(16) float  g_t2 [(size_t)NMAX * 64];
// CSR  (g_deg zeroed by scatter_kernel AFTER scan consumes it -> next replay sees zeros;
//       first call relies on module-load zero-init; deterministic across replays)
__device__ int    g_deg[NMAX];
__device__ int    g_bsum[128];
__device__ int    g_rowptr[NMAX + 1];
__device__ int    g_cursor[NMAX];
__device__ int    g_esrc[EMAX];
__device__ __align__(8) float2 g_eea[EMAX];

__device__ __forceinline__ int clampi(int v, int hi) {
    return v < 0 ? 0 : (v >= hi ? hi - 1 : v);
}
__device__ __forceinline__ uint32_t f2tf32(float f) {
    uint32_t u;
    asm("cvt.rna.tf32.f32 %0, %1;" : "=r"(u) : "f"(f));
    return u;
}
__device__ __forceinline__ void mma_tf32(float4& c, const uint32_t a[4], const uint32_t b[2]) {
    asm("mma.sync.aligned.m16n8k8.row.col.f32.tf32.tf32.f32 "
        "{%0,%1,%2,%3}, {%4,%5,%6,%7}, {%8,%9}, {%0,%1,%2,%3};"
        : "+f"(c.x), "+f"(c.y), "+f"(c.z), "+f"(c.w)
        : "r"(a[0]), "r"(a[1]), "r"(a[2]), "r"(a[3]), "r"(b[0]), "r"(b[1]));
}

// ---------------- CSR build ----------------
__global__ void hist_kernel(const int* __restrict__ ei, int E, int n) {
    int e = blockIdx.x * blockDim.x + threadIdx.x;
    if (e < E) atomicAdd(&g_deg[clampi(ei[E + e], n)], 1);
}

// scan stage 1: per-block (1024-wide, coalesced) sums of g_deg -> g_bsum
__global__ __launch_bounds__(1024)
void scan1_kernel(int n) {
    __shared__ int sh[1024];
    int t = threadIdx.x;
    int i = blockIdx.x * 1024 + t;
    sh[t] = (i < n) ? g_deg[i] : 0;
    __syncthreads();
#pragma unroll
    for (int off = 512; off > 0; off >>= 1) {
        if (t < off) sh[t] += sh[t + off];
        __syncthreads();
    }
    if (t == 0) g_bsum[blockIdx.x] = sh[0];
}

// scan stage 2: block base from prefix of g_bsum, Hillis-Steele scan of this
// block's 1024 degrees, write rowptr/cursor (all accesses coalesced)
__global__ __launch_bounds__(1024)
void scan2_kernel(int n, int nb) {
    __shared__ int spfx[128];
    __shared__ int sh[1024];
    int t = threadIdx.x;
    int i = blockIdx.x * 1024 + t;

    if (t < 128) spfx[t] = (t < nb) ? g_bsum[t] : 0;
    __syncthreads();
    // inclusive prefix over <=128 block sums (first warp-group does it via smem HS)
    if (t < 128) {
#pragma unroll
        for (int off = 1; off < 128; off <<= 1) {
            int v = (t >= off) ? spfx[t - off] : 0;
            __syncthreads();
            spfx[t] += v;
            __syncthreads();
        }
    } else {
#pragma unroll
        for (int off = 1; off < 128; off <<= 1) { __syncthreads(); __syncthreads(); }
    }
    int base = (blockIdx.x == 0) ? 0 : spfx[blockIdx.x - 1];

    int d = (i < n) ? g_deg[i] : 0;
    sh[t] = d;
    __syncthreads();
#pragma unroll
    for (int off = 1; off < 1024; off <<= 1) {
        int v = (t >= off) ? sh[t - off] : 0;
        __syncthreads();
        sh[t] += v;
        __syncthreads();
    }
    if (i < n) {
        int excl = base + sh[t] - d;
        g_rowptr[i] = excl;
        g_cursor[i] = excl;
        if (i == n - 1) g_rowptr[n] = base + sh[t];
    }
}

// scatter + re-zero g_deg for the next replay
__global__ void scatter_kernel(const int* __restrict__ ei, const float* __restrict__ ea,
                               int E, int n) {
    int e = blockIdx.x * blockDim.x + threadIdx.x;
    if (e < n) g_deg[e] = 0;
    if (e >= E) return;
    int src = clampi(ei[e], n);
    int dst = clampi(ei[E + e], n);
    int pos = atomicAdd(&g_cursor[dst], 1);
    g_esrc[pos] = src;
    g_eea[pos]  = *reinterpret_cast<const float2*>(ea + (size_t)e * 2);
}

// ---------------- tf32 tensor-core GEMM, K=128, M-tile=128, N-tile=NT (R9 proven version) ----
// EPI 0: qkv split -> q fp32 plane + interleaved kv fp16
// EPI 1: bias + resid -> C (NCOLS=128)
// EPI 2: bias + relu  -> C (NCOLS=64, NT=64)
template<int NT, int EPI>
__global__ __launch_bounds__(256)
void gemm_tf32(const float* __restrict__ A, const float* __restrict__ B,
               const float* __restrict__ bias, const float* __restrict__ resid,
               float* __restrict__ C, __half* __restrict__ Hkv, int M, int NCOLS)
{
    constexpr int WM = (NT == 128) ? 2 : 4;
    constexpr int WN = 8 / WM;
    constexpr int MFRAG = 8 / WM;
    constexpr int NFRAG = NT / (WN * 8);

    __shared__ uint32_t As[128][20];
    __shared__ uint32_t Bs[16][NT + 8];

    const int t = threadIdx.x;
    const int lane = t & 31;
    const int wid  = t >> 5;
    const int warp_m = wid / WN;
    const int warp_n = wid % WN;
    const int m0 = blockIdx.x * 128;
    const int n0 = blockIdx.y * NT;
    const int lr = lane >> 2, lc = lane & 3;

    float4 acc[MFRAG][NFRAG];
#pragma unroll
    for (int i = 0; i < MFRAG; ++i)
#pragma unroll
        for (int j = 0; j < NFRAG; ++j) acc[i][j] = make_float4(0.f, 0.f, 0.f, 0.f);

    const int arow = t >> 1;
    const int acb  = (t & 1) * 8;
    int agr = m0 + arow; if (agr >= M) agr = M - 1;
    const float* Ap = A + (size_t)agr * 128 + acb;

    const int brow = t >> 4;
    const int bcb  = (t & 15) * (NT / 16);
    const float* Bp = B + (size_t)brow * NCOLS + n0 + bcb;

    for (int k0 = 0; k0 < 128; k0 += 16) {
        float4 av0 = *reinterpret_cast<const float4*>(Ap + k0);
        float4 av1 = *reinterpret_cast<const float4*>(Ap + k0 + 4);
        As[arow][acb + 0] = f2tf32(av0.x); As[arow][acb + 1] = f2tf32(av0.y);
        As[arow][acb + 2] = f2tf32(av0.z); As[arow][acb + 3] = f2tf32(av0.w);
        As[arow][acb + 4] = f2tf32(av1.x); As[arow][acb + 5] = f2tf32(av1.y);
        As[arow][acb + 6] = f2tf32(av1.z); As[arow][acb + 7] = f2tf32(av1.w);
#pragma unroll
        for (int j = 0; j < NT / 64; ++j) {
            float4 bv = *reinterpret_cast<const float4*>(Bp + (size_t)k0 * NCOLS + j * 4);
            Bs[brow][bcb + j * 4 + 0] = f2tf32(bv.x);
            Bs[brow][bcb + j * 4 + 1] = f2tf32(bv.y);
            Bs[brow][bcb + j * 4 + 2] = f2tf32(bv.z);
            Bs[brow][bcb + j * 4 + 3] = f2tf32(bv.w);
        }
        __syncthreads();

#pragma unroll
        for (int ks = 0; ks < 16; ks += 8) {
            uint32_t afr[MFRAG][4];
#pragma unroll
            for (int fm = 0; fm < MFRAG; ++fm) {
                int mr = warp_m * (MFRAG * 16) + fm * 16 + lr;
                afr[fm][0] = As[mr][ks + lc];
                afr[fm][1] = As[mr + 8][ks + lc];
                afr[fm][2] = As[mr][ks + lc + 4];
                afr[fm][3] = As[mr + 8][ks + lc + 4];
            }
            uint32_t bfr[NFRAG][2];
#pragma unroll
            for (int fn = 0; fn < NFRAG; ++fn) {
                int nc = warp_n * (NFRAG * 8) + fn * 8 + lr;
                bfr[fn][0] = Bs[ks + lc][nc];
                bfr[fn][1] = Bs[ks + lc + 4][nc];
            }
#pragma unroll
            for (int fm = 0; fm < MFRAG; ++fm)
#pragma unroll
                for (int fn = 0; fn < NFRAG; ++fn)
                    mma_tf32(acc[fm][fn], afr[fm], bfr[fn]);
        }
        __syncthreads();
    }

    const int plane = n0 >> 7;
#pragma unroll
    for (int fm = 0; fm < MFRAG; ++fm) {
        int r0 = m0 + warp_m * (MFRAG * 16) + fm * 16 + lr;
        int r1 = r0 + 8;
#pragma unroll
        for (int fn = 0; fn < NFRAG; ++fn) {
            int cl = warp_n * (NFRAG * 8) + fn * 8 + 2 * lc;
            float4 c = acc[fm][fn];
            if (EPI == 0) {
                if (plane == 0) {
                    if (r0 < M) *reinterpret_cast<float2*>(C + (size_t)r0 * 128 + cl) = make_float2(c.x, c.y);
                    if (r1 < M) *reinterpret_cast<float2*>(C + (size_t)r1 * 128 + cl) = make_float2(c.z, c.w);
                } else {
                    int hi = ((cl >> 2) << 3) + (cl & 3) + ((plane == 2) ? 4 : 0);
                    if (r0 < M) *reinterpret_cast<__half2*>(Hkv + (size_t)r0 * 256 + hi) = __floats2half2_rn(c.x, c.y);
                    if (r1 < M) *reinterpret_cast<__half2*>(Hkv + (size_t)r1 * 256 + hi) = __floats2half2_rn(c.z, c.w);
                }
            } else {
                int col = n0 + cl;
                float b0 = bias[col], b1 = bias[col + 1];
                if (EPI == 1) {
                    if (r0 < M) {
                        float2 rr = *reinterpret_cast<const float2*>(resid + (size_t)r0 * NCOLS + col);
                        *reinterpret_cast<float2*>(C + (size_t)r0 * NCOLS + col) =
                            make_float2(c.x + b0 + rr.x, c.y + b1 + rr.y);
                    }
                    if (r1 < M) {
                        float2 rr = *reinterpret_cast<const float2*>(resid + (size_t)r1 * NCOLS + col);
                        *reinterpret_cast<float2*>(C + (size_t)r1 * NCOLS + col) =
                            make_float2(c.z + b0 + rr.x, c.w + b1 + rr.y);
                    }
                } else {
                    if (r0 < M)
                        *reinterpret_cast<float2*>(C + (size_t)r0 * NCOLS + col) =
                            make_float2(fmaxf(c.x + b0, 0.f), fmaxf(c.y + b1, 0.f));
                    if (r1 < M)
                        *reinterpret_cast<float2*>(C + (size_t)r1 * NCOLS + col) =
                            make_float2(fmaxf(c.z + b0, 0.f), fmaxf(c.w + b1, 0.f));
                }
            }
        }
    }
}

// ---------------- fused CSR attention: 1 warp/node, EPW=8, ONE LDG.128 per edge ----------------
__global__ __launch_bounds__(128)
void fused_attn(const float* __restrict__ Wedge, int n)
{
    constexpr int EPW = 8;
    int i    = (blockIdx.x * blockDim.x + threadIdx.x) >> 5;
    int lane = threadIdx.x & 31;
    if (i >= n) return;
    int hg = lane >> 2;

    int beg = g_rowptr[i];
    int end = g_rowptr[i + 1];

    float4 q4 = *reinterpret_cast<const float4*>(g_q + (size_t)i * 128 + lane * 4);
    q4.x *= 0.25f; q4.y *= 0.25f; q4.z *= 0.25f; q4.w *= 0.25f;
    float w0 = Wedge[hg], w1 = Wedge[8 + hg];

    float4 accv = {0.f, 0.f, 0.f, 0.f};
    float  accd = 0.f;

    for (int j = beg; j < end; j += EPW) {
        int   idx[EPW];
        float sb[EPW];
#pragma unroll
        for (int u = 0; u < EPW; ++u) {
            int jj = min(j + u, end - 1);
            idx[u] = __ldg(g_esrc + jj);
            float2 ea2 = g_eea[jj];
            sb[u] = ea2.x * w0 + ea2.y * w1;
        }
        uint4 kv[EPW];
#pragma unroll
        for (int u = 0; u < EPW; ++u)
            kv[u] = *reinterpret_cast<const uint4*>(g_kv + (size_t)idx[u] * 256 + lane * 8);

        float ex[EPW];
#pragma unroll
        for (int u = 0; u < EPW; ++u) {
            float2 ka = __half22float2(*reinterpret_cast<const __half2*>(&kv[u].x));
            float2 kb = __half22float2(*reinterpret_cast<const __half2*>(&kv[u].y));
            float p = q4.x * ka.x + q4.y * ka.y + q4.z * kb.x + q4.w * kb.y;
            p += __shfl_xor_sync(0xffffffffu, p, 1);
            p += __shfl_xor_sync(0xffffffffu, p, 2);
            float e = __expf(p + sb[u]);
            ex[u] = (j + u < end) ? e : 0.f;
            accd += ex[u];
        }
#pragma unroll
        for (int u = 0; u < EPW; ++u) {
            float2 va = __half22float2(*reinterpret_cast<const __half2*>(&kv[u].z));
            float2 vb = __half22float2(*reinterpret_cast<const __half2*>(&kv[u].w));
            accv.x += ex[u] * va.x;
            accv.y += ex[u] * va.y;
            accv.z += ex[u] * vb.x;
            accv.w += ex[u] * vb.y;
        }
    }

    float invd = __fdividef(1.f, accd + 1e-16f);
    float4 o = {accv.x * invd, accv.y * invd, accv.z * invd, accv.w * invd};
    *reinterpret_cast<float4*>(g_agg + (size_t)i * 128 + lane * 4) = o;
}

// ---------------- layernorm ----------------
__global__ __launch_bounds__(256)
void ln_kernel(const float* __restrict__ lw, const float* __restrict__ lb, int n)
{
    int node = (blockIdx.x * blockDim.x + threadIdx.x) >> 5;
    int lane = threadIdx.x & 31;
    if (node >= n) return;

    float4 v = *reinterpret_cast<const float4*>(g_h + (size_t)node * 128 + lane * 4);
    float s = v.x + v.y + v.z + v.w;
    float q = v.x * v.x + v.y * v.y + v.z * v.z + v.w * v.w;
#pragma unroll
    for (int o = 16; o; o >>= 1) {
        s += __shfl_xor_sync(0xffffffffu, s, o);
        q += __shfl_xor_sync(0xffffffffu, q, o);
    }
    float mu  = s * (1.f / 128.f);
    float var = q * (1.f / 128.f) - mu * mu;
    float rs  = rsqrtf(var + 1e-5f);
    float4 w4 = *reinterpret_cast<const float4*>(lw + lane * 4);
    float4 b4 = *reinterpret_cast<const float4*>(lb + lane * 4);
    float4 o;
    o.x = (v.x - mu) * rs * w4.x + b4.x;
    o.y = (v.y - mu) * rs * w4.y + b4.y;
    o.z = (v.z - mu) * rs * w4.z + b4.z;
    o.w = (v.w - mu) * rs * w4.w + b4.w;
    *reinterpret_cast<float4*>(g_hn + (size_t)node * 128 + lane * 4) = o;
}

// ---------------- final: out[N,3] = t2[N,64] @ Wc2[64,3] + bc2 ----------------
__global__ __launch_bounds__(256)
void final_kernel(const float* __restrict__ Wc2, const float* __restrict__ bc2,
                  float* __restrict__ out, int n)
{
    int node = (blockIdx.x * blockDim.x + threadIdx.x) >> 5;
    int lane = threadIdx.x & 31;
    if (node >= n) return;

    float2 tv = *reinterpret_cast<const float2*>(g_t2 + (size_t)node * 64 + lane * 2);
    int k0 = lane * 2;
    float s0 = tv.x * Wc2[k0 * 3 + 0] + tv.y * Wc2[k0 * 3 + 3];
    float s1 = tv.x * Wc2[k0 * 3 + 1] + tv.y * Wc2[k0 * 3 + 4];
    float s2 = tv.x * Wc2[k0 * 3 + 2] + tv.y * Wc2[k0 * 3 + 5];
#pragma unroll
    for (int o = 16; o; o >>= 1) {
        s0 += __shfl_xor_sync(0xffffffffu, s0, o);
        s1 += __shfl_xor_sync(0xffffffffu, s1, o);
        s2 += __shfl_xor_sync(0xffffffffu, s2, o);
    }
    if (lane == 0) {
        out[(size_t)node * 3 + 0] = s0 + bc2[0];
        out[(size_t)node * 3 + 1] = s1 + bc2[1];
        out[(size_t)node * 3 + 2] = s2 + bc2[2];
    }
}

// ---------------- launch ----------------
extern "C" void kernel_launch(void* const* d_in, const int* in_sizes, int n_in,
                              void* d_out, int out_size)
{
    const float* x     = (const float*)d_in[0];
    const int*   ei    = (const int*)d_in[1];
    const float* ea    = (const float*)d_in[2];
    const float* Wqkv  = (const float*)d_in[3];
    const float* Wedge = (const float*)d_in[4];
    const float* Wout  = (const float*)d_in[5];
    const float* bout  = (const float*)d_in[6];
    const float* lnw   = (const float*)d_in[7];
    const float* lnb   = (const float*)d_in[8];
    const float* Wc1   = (const float*)d_in[9];
    const float* bc1   = (const float*)d_in[10];
    const float* Wc2   = (const float*)d_in[11];
    const float* bc2   = (const float*)d_in[12];
    float* out = (float*)d_out;

    const int n = in_sizes[0] / 128;
    const int E = in_sizes[1] / 2;
    const int nb = (n + 1023) >> 10;

    float *q, *agg, *h, *hn, *t2;
    __half* kv;
    cudaGetSymbolAddress((void**)&q,   g_q);
    cudaGetSymbolAddress((void**)&kv,  g_kv);
    cudaGetSymbolAddress((void**)&agg, g_agg);
    cudaGetSymbolAddress((void**)&h,   g_h);
    cudaGetSymbolAddress((void**)&hn,  g_hn);
    cudaGetSymbolAddress((void**)&t2,  g_t2);

    // 1. edge histogram (g_deg zeroed by previous scatter / module init)
    hist_kernel<<<(E + 255) / 256, 256>>>(ei, E, n);

    // 2-3. decoupled two-stage scan -> rowptr/cursor (coalesced, multi-SM)
    scan1_kernel<<<nb, 1024>>>(n);
    scan2_kernel<<<nb, 1024>>>(n, nb);

    // 4. qkv = x @ Wqkv -> q fp32 + interleaved kv fp16   <-- profiled slot
    gemm_tf32<128, 0><<<dim3((n + 127) / 128, 3), 256>>>(
        x, Wqkv, nullptr, nullptr, q, kv, n, 384);

    // 5. scatter edges into CSR (+ re-zero g_deg for next replay)
    scatter_kernel<<<(E + 255) / 256, 256>>>(ei, ea, E, n);

    // 6. fused per-node attention
    fused_attn<<<(n + 3) / 4, 128>>>(Wedge, n);

    // 7. h = agg @ Wout + bout + x
    gemm_tf32<128, 1><<<dim3((n + 127) / 128, 1), 256>>>(
        agg, Wout, bout, x, h, nullptr, n, 128);

    // 8. layernorm
    ln_kernel<<<(n + 7) / 8, 256>>>(lnw, lnb, n);

    // 9. t2 = relu(hn @ Wc1 + bc1)
    gemm_tf32<64, 2><<<dim3((n + 127) / 128, 1), 256>>>(
        hn, Wc1, bc1, nullptr, t2, nullptr, n, 64);

    // 10. out = t2 @ Wc2 + bc2
    final_kernel<<<(n + 7) / 8, 256>>>(Wc2, bc2, out, n);
}

// round 15
// speedup vs baseline: 1.5439x; 1.0761x over previous
#include <cuda_runtime.h>
#include <cuda_fp16.h>
#include <stdint.h>

#define NMAX 100000
#define EMAX 1600000

// ---------------- scratch (static device globals) ----------------
__device__ __align__(16) float  g_q  [(size_t)NMAX * 128];
// interleaved kv: per node 256 halves = [k0..3 | v0..3 | k4..7 | v4..7 | ...]
__device__ __align__(16) __half g_kv [(size_t)NMAX * 256];
__device__ __align__(16) float  g_agg[(size_t)NMAX * 128];
__device__ __align__(16) float  g_h  [(size_t)NMAX * 128];
__device__ __align__(16) float  g_hn [(size_t)NMAX * 128];
__device__ __align__(16) float  g_t2 [(size_t)NMAX * 64];
// n-major fp16 weights (transposed every launch by prep_kernel)
__device__ __align__(16) __half g_wqkvT[384 * 128];
__device__ __align__(16) __half g_woutT[128 * 128];
__device__ __align__(16) __half g_wc1T [64 * 128];
// CSR  (g_deg zeroed by scatter_kernel AFTER scan consumes it)
__device__ int    g_deg[NMAX];
__device__ int    g_bsum[128];
__device__ int    g_rowptr[NMAX + 1];
__device__ int    g_cursor[NMAX];
__device__ int    g_esrc[EMAX];
__device__ __align__(8) float2 g_eea[EMAX];

__device__ __forceinline__ int clampi(int v, int hi) {
    return v < 0 ? 0 : (v >= hi ? hi - 1 : v);
}
__device__ __forceinline__ void mma_fp16(float4& c, const uint32_t a[4], const uint32_t b[2]) {
    asm("mma.sync.aligned.m16n8k16.row.col.f32.f16.f16.f32 "
        "{%0,%1,%2,%3}, {%4,%5,%6,%7}, {%8,%9}, {%0,%1,%2,%3};"
        : "+f"(c.x), "+f"(c.y), "+f"(c.z), "+f"(c.w)
        : "r"(a[0]), "r"(a[1]), "r"(a[2]), "r"(a[3]), "r"(b[0]), "r"(b[1]));
}

// ---------------- weight prep: W[k][n] fp32 -> WT[n][k] fp16 ----------------
__global__ void prep_kernel(const float* __restrict__ Wqkv,
                            const float* __restrict__ Wout,
                            const float* __restrict__ Wc1)
{
    int i = blockIdx.x * blockDim.x + threadIdx.x;
    if (i < 384 * 128) {
        int nn = i >> 7, k = i & 127;
        g_wqkvT[i] = __float2half(Wqkv[k * 384 + nn]);
    } else if (i < 384 * 128 + 128 * 128) {
        int j = i - 384 * 128;
        int nn = j >> 7, k = j & 127;
        g_woutT[j] = __float2half(Wout[k * 128 + nn]);
    } else if (i < 384 * 128 + 128 * 128 + 64 * 128) {
        int j = i - 384 * 128 - 128 * 128;
        int nn = j >> 7, k = j & 127;
        g_wc1T[j] = __float2half(Wc1[k * 64 + nn]);
    }
}

// ---------------- CSR build ----------------
__global__ void hist_kernel(const int* __restrict__ ei, int E, int n) {
    int e = blockIdx.x * blockDim.x + threadIdx.x;
    if (e < E) atomicAdd(&g_deg[clampi(ei[E + e], n)], 1);
}
__global__ __launch_bounds__(1024)
void scan1_kernel(int n) {
    __shared__ int sh[1024];
    int t = threadIdx.x;
    int i = blockIdx.x * 1024 + t;
    sh[t] = (i < n) ? g_deg[i] : 0;
    __syncthreads();
#pragma unroll
    for (int off = 512; off > 0; off >>= 1) {
        if (t < off) sh[t] += sh[t + off];
        __syncthreads();
    }
    if (t == 0) g_bsum[blockIdx.x] = sh[0];
}
__global__ __launch_bounds__(1024)
void scan2_kernel(int n, int nb) {
    __shared__ int spfx[128];
    __shared__ int sh[1024];
    int t = threadIdx.x;
    int i = blockIdx.x * 1024 + t;

    if (t < 128) spfx[t] = (t < nb) ? g_bsum[t] : 0;
    __syncthreads();
    if (t < 128) {
#pragma unroll
        for (int off = 1; off < 128; off <<= 1) {
            int v = (t >= off) ? spfx[t - off] : 0;
            __syncthreads();
            spfx[t] += v;
            __syncthreads();
        }
    } else {
#pragma unroll
        for (int off = 1; off < 128; off <<= 1) { __syncthreads(); __syncthreads(); }
    }
    int base = (blockIdx.x == 0) ? 0 : spfx[blockIdx.x - 1];

    int d = (i < n) ? g_deg[i] : 0;
    sh[t] = d;
    __syncthreads();
#pragma unroll
    for (int off = 1; off < 1024; off <<= 1) {
        int v = (t >= off) ? sh[t - off] : 0;
        __syncthreads();
        sh[t] += v;
        __syncthreads();
    }
    if (i < n) {
        int excl = base + sh[t] - d;
        g_rowptr[i] = excl;
        g_cursor[i] = excl;
        if (i == n - 1) g_rowptr[n] = base + sh[t];
    }
}
__global__ void scatter_kernel(const int* __restrict__ ei, const float* __restrict__ ea,
                               int E, int n) {
    int e = blockIdx.x * blockDim.x + threadIdx.x;
    if (e < n) g_deg[e] = 0;
    if (e >= E) return;
    int src = clampi(ei[e], n);
    int dst = clampi(ei[E + e], n);
    int pos = atomicAdd(&g_cursor[dst], 1);
    g_esrc[pos] = src;
    g_eea[pos]  = *reinterpret_cast<const float2*>(ea + (size_t)e * 2);
}

// ---------------- fp16 tensor-core GEMM (m16n8k16), K=128, M-tile=128, N-tile=NT ----------
// A fp32 [M][128] converted in-flight; BT fp16 n-major [ncols][128].
// EPI 0: qkv split -> q fp32 plane + interleaved kv fp16
// EPI 1: bias + resid -> C (NCOLS=128)
// EPI 2: bias + relu  -> C (NCOLS=64, NT=64)
template<int NT, int EPI>
__global__ __launch_bounds__(256)
void gemm_fp16(const float* __restrict__ A, const __half* __restrict__ BT,
               const float* __restrict__ bias, const float* __restrict__ resid,
               float* __restrict__ C, __half* __restrict__ Hkv, int M, int NCOLS)
{
    constexpr int WM = (NT == 128) ? 2 : 4;
    constexpr int WN = 8 / WM;
    constexpr int MFRAG = 8 / WM;           // m16 frags per warp
    constexpr int NFRAG = NT / (WN * 8);    // n8 frags per warp
    constexpr int PITCH = 24;               // halves per smem row (conflict-free frags)

    __shared__ __half As[128][PITCH];
    __shared__ __half Bs[NT][PITCH];

    const int t = threadIdx.x;
    const int lane = t & 31;
    const int wid  = t >> 5;
    const int warp_m = wid / WN;
    const int warp_n = wid % WN;
    const int m0 = blockIdx.x * 128;
    const int n0 = blockIdx.y * NT;
    const int lr = lane >> 2, lc = lane & 3;

    float4 acc[MFRAG][NFRAG];
#pragma unroll
    for (int i = 0; i < MFRAG; ++i)
#pragma unroll
        for (int j = 0; j < NFRAG; ++j) acc[i][j] = make_float4(0.f, 0.f, 0.f, 0.f);

    // A staging: thread covers row t>>1, k-sub (t&1)*8
    const int arow = t >> 1;
    const int acb  = (t & 1) * 8;
    int agr = m0 + arow; if (agr >= M) agr = M - 1;
    const float* Ap = A + (size_t)agr * 128 + acb;

    // B staging from n-major fp16: NT=128 -> row t>>1, sub (t&1)*8 (uint4);
    //                              NT=64  -> row t>>2, sub (t&3)*4 (uint2)
    const int brow = (NT == 128) ? (t >> 1) : (t >> 2);
    const int bcb  = (NT == 128) ? ((t & 1) * 8) : ((t & 3) * 4);
    const __half* Bp = BT + (size_t)(n0 + brow) * 128 + bcb;

    for (int k0 = 0; k0 < 128; k0 += 16) {
        // stage A (fp32 -> fp16)
        float4 av0 = *reinterpret_cast<const float4*>(Ap + k0);
        float4 av1 = *reinterpret_cast<const float4*>(Ap + k0 + 4);
        __half2* asp = reinterpret_cast<__half2*>(&As[arow][acb]);
        asp[0] = __floats2half2_rn(av0.x, av0.y);
        asp[1] = __floats2half2_rn(av0.z, av0.w);
        asp[2] = __floats2half2_rn(av1.x, av1.y);
        asp[3] = __floats2half2_rn(av1.z, av1.w);
        // stage B (already fp16, coalesced row loads)
        if (NT == 128) {
            uint4 bv = *reinterpret_cast<const uint4*>(Bp + k0);
            uint32_t* bsp = reinterpret_cast<uint32_t*>(&Bs[brow][bcb]);
            bsp[0] = bv.x; bsp[1] = bv.y; bsp[2] = bv.z; bsp[3] = bv.w;
        } else {
            uint2 bv = *reinterpret_cast<const uint2*>(Bp + k0);
            uint32_t* bsp = reinterpret_cast<uint32_t*>(&Bs[brow][bcb]);
            bsp[0] = bv.x; bsp[1] = bv.y;
        }
        __syncthreads();

        uint32_t afr[MFRAG][4];
#pragma unroll
        for (int fm = 0; fm < MFRAG; ++fm) {
            int mr = warp_m * (MFRAG * 16) + fm * 16 + lr;
            afr[fm][0] = *reinterpret_cast<const uint32_t*>(&As[mr][2 * lc]);
            afr[fm][1] = *reinterpret_cast<const uint32_t*>(&As[mr + 8][2 * lc]);
            afr[fm][2] = *reinterpret_cast<const uint32_t*>(&As[mr][2 * lc + 8]);
            afr[fm][3] = *reinterpret_cast<const uint32_t*>(&As[mr + 8][2 * lc + 8]);
        }
        uint32_t bfr[NFRAG][2];
#pragma unroll
        for (int fn = 0; fn < NFRAG; ++fn) {
            int nc = warp_n * (NFRAG * 8) + fn * 8 + lr;
            bfr[fn][0] = *reinterpret_cast<const uint32_t*>(&Bs[nc][2 * lc]);
            bfr[fn][1] = *reinterpret_cast<const uint32_t*>(&Bs[nc][2 * lc + 8]);
        }
#pragma unroll
        for (int fm = 0; fm < MFRAG; ++fm)
#pragma unroll
            for (int fn = 0; fn < NFRAG; ++fn)
                mma_fp16(acc[fm][fn], afr[fm], bfr[fn]);
        __syncthreads();
    }

    const int plane = n0 >> 7;
#pragma unroll
    for (int fm = 0; fm < MFRAG; ++fm) {
        int r0 = m0 + warp_m * (MFRAG * 16) + fm * 16 + lr;
        int r1 = r0 + 8;
#pragma unroll
        for (int fn = 0; fn < NFRAG; ++fn) {
            int cl = warp_n * (NFRAG * 8) + fn * 8 + 2 * lc;
            float4 c = acc[fm][fn];
            if (EPI == 0) {
                if (plane == 0) {
                    if (r0 < M) *reinterpret_cast<float2*>(C + (size_t)r0 * 128 + cl) = make_float2(c.x, c.y);
                    if (r1 < M) *reinterpret_cast<float2*>(C + (size_t)r1 * 128 + cl) = make_float2(c.z, c.w);
                } else {
                    int hi = ((cl >> 2) << 3) + (cl & 3) + ((plane == 2) ? 4 : 0);
                    if (r0 < M) *reinterpret_cast<__half2*>(Hkv + (size_t)r0 * 256 + hi) = __floats2half2_rn(c.x, c.y);
                    if (r1 < M) *reinterpret_cast<__half2*>(Hkv + (size_t)r1 * 256 + hi) = __floats2half2_rn(c.z, c.w);
                }
            } else {
                int col = n0 + cl;
                float b0 = bias[col], b1 = bias[col + 1];
                if (EPI == 1) {
                    if (r0 < M) {
                        float2 rr = *reinterpret_cast<const float2*>(resid + (size_t)r0 * NCOLS + col);
                        *reinterpret_cast<float2*>(C + (size_t)r0 * NCOLS + col) =
                            make_float2(c.x + b0 + rr.x, c.y + b1 + rr.y);
                    }
                    if (r1 < M) {
                        float2 rr = *reinterpret_cast<const float2*>(resid + (size_t)r1 * NCOLS + col);
                        *reinterpret_cast<float2*>(C + (size_t)r1 * NCOLS + col) =
                            make_float2(c.z + b0 + rr.x, c.w + b1 + rr.y);
                    }
                } else {
                    if (r0 < M)
                        *reinterpret_cast<float2*>(C + (size_t)r0 * NCOLS + col) =
                            make_float2(fmaxf(c.x + b0, 0.f), fmaxf(c.y + b1, 0.f));
                    if (r1 < M)
                        *reinterpret_cast<float2*>(C + (size_t)r1 * NCOLS + col) =
                            make_float2(fmaxf(c.z + b0, 0.f), fmaxf(c.w + b1, 0.f));
                }
            }
        }
    }
}

// ---------------- fused CSR attention: 1 warp/node, EPW=8, ONE LDG.128 per edge ----------------
__global__ __launch_bounds__(128)
void fused_attn(const float* __restrict__ Wedge, int n)
{
    constexpr int EPW = 8;
    int i    = (blockIdx.x * blockDim.x + threadIdx.x) >> 5;
    int lane = threadIdx.x & 31;
    if (i >= n) return;
    int hg = lane >> 2;

    int beg = g_rowptr[i];
    int end = g_rowptr[i + 1];

    float4 q4 = *reinterpret_cast<const float4*>(g_q + (size_t)i * 128 + lane * 4);
    q4.x *= 0.25f; q4.y *= 0.25f; q4.z *= 0.25f; q4.w *= 0.25f;
    float w0 = Wedge[hg], w1 = Wedge[8 + hg];

    float4 accv = {0.f, 0.f, 0.f, 0.f};
    float  accd = 0.f;

    for (int j = beg; j < end; j += EPW) {
        int   idx[EPW];
        float sb[EPW];
#pragma unroll
        for (int u = 0; u < EPW; ++u) {
            int jj = min(j + u, end - 1);
            idx[u] = __ldg(g_esrc + jj);
            float2 ea2 = g_eea[jj];
            sb[u] = ea2.x * w0 + ea2.y * w1;
        }
        uint4 kv[EPW];
#pragma unroll
        for (int u = 0; u < EPW; ++u)
            kv[u] = *reinterpret_cast<const uint4*>(g_kv + (size_t)idx[u] * 256 + lane * 8);

        float ex[EPW];
#pragma unroll
        for (int u = 0; u < EPW; ++u) {
            float2 ka = __half22float2(*reinterpret_cast<const __half2*>(&kv[u].x));
            float2 kb = __half22float2(*reinterpret_cast<const __half2*>(&kv[u].y));
            float p = q4.x * ka.x + q4.y * ka.y + q4.z * kb.x + q4.w * kb.y;
            p += __shfl_xor_sync(0xffffffffu, p, 1);
            p += __shfl_xor_sync(0xffffffffu, p, 2);
            float e = __expf(p + sb[u]);
            ex[u] = (j + u < end) ? e : 0.f;
            accd += ex[u];
        }
#pragma unroll
        for (int u = 0; u < EPW; ++u) {
            float2 va = __half22float2(*reinterpret_cast<const __half2*>(&kv[u].z));
            float2 vb = __half22float2(*reinterpret_cast<const __half2*>(&kv[u].w));
            accv.x += ex[u] * va.x;
            accv.y += ex[u] * va.y;
            accv.z += ex[u] * vb.x;
            accv.w += ex[u] * vb.y;
        }
    }

    float invd = __fdividef(1.f, accd + 1e-16f);
    float4 o = {accv.x * invd, accv.y * invd, accv.z * invd, accv.w * invd};
    *reinterpret_cast<float4*>(g_agg + (size_t)i * 128 + lane * 4) = o;
}

// ---------------- layernorm ----------------
__global__ __launch_bounds__(256)
void ln_kernel(const float* __restrict__ lw, const float* __restrict__ lb, int n)
{
    int node = (blockIdx.x * blockDim.x + threadIdx.x) >> 5;
    int lane = threadIdx.x & 31;
    if (node >= n) return;

    float4 v = *reinterpret_cast<const float4*>(g_h + (size_t)node * 128 + lane * 4);
    float s = v.x + v.y + v.z + v.w;
    float q = v.x * v.x + v.y * v.y + v.z * v.z + v.w * v.w;
#pragma unroll
    for (int o = 16; o; o >>= 1) {
        s += __shfl_xor_sync(0xffffffffu, s, o);
        q += __shfl_xor_sync(0xffffffffu, q, o);
    }
    float mu  = s * (1.f / 128.f);
    float var = q * (1.f / 128.f) - mu * mu;
    float rs  = rsqrtf(var + 1e-5f);
    float4 w4 = *reinterpret_cast<const float4*>(lw + lane * 4);
    float4 b4 = *reinterpret_cast<const float4*>(lb + lane * 4);
    float4 o;
    o.x = (v.x - mu) * rs * w4.x + b4.x;
    o.y = (v.y - mu) * rs * w4.y + b4.y;
    o.z = (v.z - mu) * rs * w4.z + b4.z;
    o.w = (v.w - mu) * rs * w4.w + b4.w;
    *reinterpret_cast<float4*>(g_hn + (size_t)node * 128 + lane * 4) = o;
}

// ---------------- final: out[N,3] = t2[N,64] @ Wc2[64,3] + bc2 ----------------
__global__ __launch_bounds__(256)
void final_kernel(const float* __restrict__ Wc2, const float* __restrict__ bc2,
                  float* __restrict__ out, int n)
{
    int node = (blockIdx.x * blockDim.x + threadIdx.x) >> 5;
    int lane = threadIdx.x & 31;
    if (node >= n) return;

    float2 tv = *reinterpret_cast<const float2*>(g_t2 + (size_t)node * 64 + lane * 2);
    int k0 = lane * 2;
    float s0 = tv.x * Wc2[k0 * 3 + 0] + tv.y * Wc2[k0 * 3 + 3];
    float s1 = tv.x * Wc2[k0 * 3 + 1] + tv.y * Wc2[k0 * 3 + 4];
    float s2 = tv.x * Wc2[k0 * 3 + 2] + tv.y * Wc2[k0 * 3 + 5];
#pragma unroll
    for (int o = 16; o; o >>= 1) {
        s0 += __shfl_xor_sync(0xffffffffu, s0, o);
        s1 += __shfl_xor_sync(0xffffffffu, s1, o);
        s2 += __shfl_xor_sync(0xffffffffu, s2, o);
    }
    if (lane == 0) {
        out[(size_t)node * 3 + 0] = s0 + bc2[0];
        out[(size_t)node * 3 + 1] = s1 + bc2[1];
        out[(size_t)node * 3 + 2] = s2 + bc2[2];
    }
}

// ---------------- launch ----------------
extern "C" void kernel_launch(void* const* d_in, const int* in_sizes, int n_in,
                              void* d_out, int out_size)
{
    const float* x     = (const float*)d_in[0];
    const int*   ei    = (const int*)d_in[1];
    const float* ea    = (const float*)d_in[2];
    const float* Wqkv  = (const float*)d_in[3];
    const float* Wedge = (const float*)d_in[4];
    const float* Wout  = (const float*)d_in[5];
    const float* bout  = (const float*)d_in[6];
    const float* lnw   = (const float*)d_in[7];
    const float* lnb   = (const float*)d_in[8];
    const float* Wc1   = (const float*)d_in[9];
    const float* bc1   = (const float*)d_in[10];
    const float* Wc2   = (const float*)d_in[11];
    const float* bc2   = (const float*)d_in[12];
    float* out = (float*)d_out;

    const int n = in_sizes[0] / 128;
    const int E = in_sizes[1] / 2;
    const int nb = (n + 1023) >> 10;

    float *q, *agg, *h, *hn, *t2;
    __half *kv, *wqkvT, *woutT, *wc1T;
    cudaGetSymbolAddress((void**)&q,     g_q);
    cudaGetSymbolAddress((void**)&kv,    g_kv);
    cudaGetSymbolAddress((void**)&agg,   g_agg);
    cudaGetSymbolAddress((void**)&h,     g_h);
    cudaGetSymbolAddress((void**)&hn,    g_hn);
    cudaGetSymbolAddress((void**)&t2,    g_t2);
    cudaGetSymbolAddress((void**)&wqkvT, g_wqkvT);
    cudaGetSymbolAddress((void**)&woutT, g_woutT);
    cudaGetSymbolAddress((void**)&wc1T,  g_wc1T);

    // 1. edge histogram
    hist_kernel<<<(E + 255) / 256, 256>>>(ei, E, n);

    // 2. block sums for scan
    scan1_kernel<<<nb, 1024>>>(n);

    // 3. weight transpose+fp16 convert
    prep_kernel<<<(73728 + 255) / 256, 256>>>(Wqkv, Wout, Wc1);

    // 4. qkv = x @ Wqkv -> q fp32 + interleaved kv fp16   <-- profiled slot
    gemm_fp16<128, 0><<<dim3((n + 127) / 128, 3), 256>>>(
        x, wqkvT, nullptr, nullptr, q, kv, n, 384);

    // 5. finish scan -> rowptr/cursor
    scan2_kernel<<<nb, 1024>>>(n, nb);

    // 6. scatter edges into CSR (+ re-zero g_deg for next replay)
    scatter_kernel<<<(E + 255) / 256, 256>>>(ei, ea, E, n);

    // 7. fused per-node attention
    fused_attn<<<(n + 3) / 4, 128>>>(Wedge, n);

    // 8. h = agg @ Wout + bout + x
    gemm_fp16<128, 1><<<dim3((n + 127) / 128, 1), 256>>>(
        agg, woutT, bout, x, h, nullptr, n, 128);

    // 9. layernorm
    ln_kernel<<<(n + 7) / 8, 256>>>(lnw, lnb, n);

    // 10. t2 = relu(hn @ Wc1 + bc1)
    gemm_fp16<64, 2><<<dim3((n + 127) / 128, 1), 256>>>(
        hn, wc1T, bc1, nullptr, t2, nullptr, n, 64);

    // 11. out = t2 @ Wc2 + bc2
    final_kernel<<<(n + 7) / 8, 256>>>(Wc2, bc2, out, n);
}

// round 16
// speedup vs baseline: 1.6388x; 1.0615x over previous
#include <cuda_runtime.h>
#include <cuda_fp16.h>
#include <stdint.h>

#define NMAX 100000
#define EMAX 1600000

// ---------------- scratch (static device globals) ----------------
__device__ __align__(16) float  g_q  [(size_t)NMAX * 128];
// interleaved kv: per node 256 halves = [k0..3 | v0..3 | k4..7 | v4..7 | ...]
__device__ __align__(16) __half g_kv [(size_t)NMAX * 256];
__device__ __align__(16) float  g_agg[(size_t)NMAX * 128];
__device__ __align__(16) float  g_h  [(size_t)NMAX * 128];
__device__ __align__(16) float  g_hn [(size_t)NMAX * 128];
__device__ __align__(16) float  g_t2 [(size_t)NMAX * 64];
// n-major fp16 weights (transposed every launch by prep_kernel)
__device__ __align__(16) __half g_wqkvT[384 * 128];
__device__ __align__(16) __half g_woutT[128 * 128];
__device__ __align__(16) __half g_wc1T [64 * 128];
// CSR  (g_deg zeroed by scatter_kernel AFTER scan consumes it)
__device__ int    g_deg[NMAX];
__device__ int    g_bsum[128];
__device__ int    g_rowptr[NMAX + 1];
__device__ int    g_cursor[NMAX];
__device__ int    g_esrc[EMAX];
__device__ __align__(8) float2 g_eea[EMAX];

__device__ __forceinline__ int clampi(int v, int hi) {
    return v < 0 ? 0 : (v >= hi ? hi - 1 : v);
}
__device__ __forceinline__ void mma_fp16(float4& c, const uint32_t a[4], const uint32_t b[2]) {
    asm("mma.sync.aligned.m16n8k16.row.col.f32.f16.f16.f32 "
        "{%0,%1,%2,%3}, {%4,%5,%6,%7}, {%8,%9}, {%0,%1,%2,%3};"
        : "+f"(c.x), "+f"(c.y), "+f"(c.z), "+f"(c.w)
        : "r"(a[0]), "r"(a[1]), "r"(a[2]), "r"(a[3]), "r"(b[0]), "r"(b[1]));
}
__device__ __forceinline__ uint32_t h2u(__half2 h) {
    return *reinterpret_cast<uint32_t*>(&h);
}

// ---------------- weight prep: W[k][n] fp32 -> WT[n][k] fp16 ----------------
__global__ void prep_kernel(const float* __restrict__ Wqkv,
                            const float* __restrict__ Wout,
                            const float* __restrict__ Wc1)
{
    int i = blockIdx.x * blockDim.x + threadIdx.x;
    if (i < 384 * 128) {
        int nn = i >> 7, k = i & 127;
        g_wqkvT[i] = __float2half(Wqkv[k * 384 + nn]);
    } else if (i < 384 * 128 + 128 * 128) {
        int j = i - 384 * 128;
        int nn = j >> 7, k = j & 127;
        g_woutT[j] = __float2half(Wout[k * 128 + nn]);
    } else if (i < 384 * 128 + 128 * 128 + 64 * 128) {
        int j = i - 384 * 128 - 128 * 128;
        int nn = j >> 7, k = j & 127;
        g_wc1T[j] = __float2half(Wc1[k * 64 + nn]);
    }
}

// ---------------- CSR build ----------------
__global__ void hist_kernel(const int* __restrict__ ei, int E, int n) {
    int e = blockIdx.x * blockDim.x + threadIdx.x;
    if (e < E) atomicAdd(&g_deg[clampi(ei[E + e], n)], 1);
}
__global__ __launch_bounds__(1024)
void scan1_kernel(int n) {
    __shared__ int sh[1024];
    int t = threadIdx.x;
    int i = blockIdx.x * 1024 + t;
    sh[t] = (i < n) ? g_deg[i] : 0;
    __syncthreads();
#pragma unroll
    for (int off = 512; off > 0; off >>= 1) {
        if (t < off) sh[t] += sh[t + off];
        __syncthreads();
    }
    if (t == 0) g_bsum[blockIdx.x] = sh[0];
}
__global__ __launch_bounds__(1024)
void scan2_kernel(int n, int nb) {
    __shared__ int spfx[128];
    __shared__ int sh[1024];
    int t = threadIdx.x;
    int i = blockIdx.x * 1024 + t;

    if (t < 128) spfx[t] = (t < nb) ? g_bsum[t] : 0;
    __syncthreads();
    if (t < 128) {
#pragma unroll
        for (int off = 1; off < 128; off <<= 1) {
            int v = (t >= off) ? spfx[t - off] : 0;
            __syncthreads();
            spfx[t] += v;
            __syncthreads();
        }
    } else {
#pragma unroll
        for (int off = 1; off < 128; off <<= 1) { __syncthreads(); __syncthreads(); }
    }
    int base = (blockIdx.x == 0) ? 0 : spfx[blockIdx.x - 1];

    int d = (i < n) ? g_deg[i] : 0;
    sh[t] = d;
    __syncthreads();
#pragma unroll
    for (int off = 1; off < 1024; off <<= 1) {
        int v = (t >= off) ? sh[t - off] : 0;
        __syncthreads();
        sh[t] += v;
        __syncthreads();
    }
    if (i < n) {
        int excl = base + sh[t] - d;
        g_rowptr[i] = excl;
        g_cursor[i] = excl;
        if (i == n - 1) g_rowptr[n] = base + sh[t];
    }
}
__global__ void scatter_kernel(const int* __restrict__ ei, const float* __restrict__ ea,
                               int E, int n) {
    int e = blockIdx.x * blockDim.x + threadIdx.x;
    if (e < n) g_deg[e] = 0;
    if (e >= E) return;
    int src = clampi(ei[e], n);
    int dst = clampi(ei[E + e], n);
    int pos = atomicAdd(&g_cursor[dst], 1);
    g_esrc[pos] = src;
    g_eea[pos]  = *reinterpret_cast<const float2*>(ea + (size_t)e * 2);
}

// ---------------- qkv GEMM: A read ONCE, all 3 planes per block ----------------
// A fp32 [M][128] -> smem fp16 (full 128x128 tile); B n-major fp16, 16-k chunks
// double-buffered. Outputs: plane 0 -> q fp32, planes 1/2 -> interleaved kv fp16.
__global__ __launch_bounds__(256)
void gemm_qkv(const float* __restrict__ A, const __half* __restrict__ BT,
              float* __restrict__ Cq, __half* __restrict__ Hkv, int M)
{
    __shared__ __half As[128][136];       // full A tile (pitch 136 -> conflict-free frags)
    __shared__ __half Bs[2][128][24];     // double-buffered B chunk [n][k16]

    const int t = threadIdx.x;
    const int lane = t & 31;
    const int wid  = t >> 5;
    const int warp_m = wid >> 2;          // 0..1
    const int warp_n = wid & 3;           // 0..3
    const int m0 = blockIdx.x * 128;
    const int lr = lane >> 2, lc = lane & 3;

    // ---- stage full A tile (fp32 -> fp16), one time ----
    {
        int arow = t >> 1;
        int acb  = (t & 1) * 64;
        int agr = m0 + arow; if (agr >= M) agr = M - 1;
        const float* Ap = A + (size_t)agr * 128 + acb;
#pragma unroll
        for (int j = 0; j < 8; ++j) {
            float4 v0 = *reinterpret_cast<const float4*>(Ap + j * 8);
            float4 v1 = *reinterpret_cast<const float4*>(Ap + j * 8 + 4);
            uint4 u;
            u.x = h2u(__floats2half2_rn(v0.x, v0.y));
            u.y = h2u(__floats2half2_rn(v0.z, v0.w));
            u.z = h2u(__floats2half2_rn(v1.x, v1.y));
            u.w = h2u(__floats2half2_rn(v1.z, v1.w));
            *reinterpret_cast<uint4*>(&As[arow][acb + j * 8]) = u;
        }
    }
    const int brow = t >> 1;              // B staging row (0..127)
    const int bcb  = (t & 1) * 8;         // B staging k-offset (halves)
    __syncthreads();

    for (int plane = 0; plane < 3; ++plane) {
        const __half* Bpl = BT + (size_t)plane * 128 * 128;

        float4 acc[4][4];
#pragma unroll
        for (int i = 0; i < 4; ++i)
#pragma unroll
            for (int j = 0; j < 4; ++j) acc[i][j] = make_float4(0.f, 0.f, 0.f, 0.f);

        // stage chunk 0
        *reinterpret_cast<uint4*>(&Bs[0][brow][bcb]) =
            *reinterpret_cast<const uint4*>(Bpl + (size_t)brow * 128 + bcb);
        __syncthreads();

#pragma unroll
        for (int kc = 0; kc < 8; ++kc) {
            const int buf = kc & 1;
            // prefetch next chunk into the other buffer (overlaps MMA below)
            if (kc + 1 < 8)
                *reinterpret_cast<uint4*>(&Bs[buf ^ 1][brow][bcb]) =
                    *reinterpret_cast<const uint4*>(Bpl + (size_t)brow * 128 + (kc + 1) * 16 + bcb);

            const int k0 = kc * 16;
            uint32_t afr[4][4];
#pragma unroll
            for (int fm = 0; fm < 4; ++fm) {
                int mr = warp_m * 64 + fm * 16 + lr;
                afr[fm][0] = *reinterpret_cast<const uint32_t*>(&As[mr][k0 + 2 * lc]);
                afr[fm][1] = *reinterpret_cast<const uint32_t*>(&As[mr + 8][k0 + 2 * lc]);
                afr[fm][2] = *reinterpret_cast<const uint32_t*>(&As[mr][k0 + 2 * lc + 8]);
                afr[fm][3] = *reinterpret_cast<const uint32_t*>(&As[mr + 8][k0 + 2 * lc + 8]);
            }
            uint32_t bfr[4][2];
#pragma unroll
            for (int fn = 0; fn < 4; ++fn) {
                int nc = warp_n * 32 + fn * 8 + lr;
                bfr[fn][0] = *reinterpret_cast<const uint32_t*>(&Bs[buf][nc][2 * lc]);
                bfr[fn][1] = *reinterpret_cast<const uint32_t*>(&Bs[buf][nc][2 * lc + 8]);
            }
#pragma unroll
            for (int fm = 0; fm < 4; ++fm)
#pragma unroll
                for (int fn = 0; fn < 4; ++fn)
                    mma_fp16(acc[fm][fn], afr[fm], bfr[fn]);
            __syncthreads();
        }

        // ---- epilogue for this plane ----
#pragma unroll
        for (int fm = 0; fm < 4; ++fm) {
            int r0 = m0 + warp_m * 64 + fm * 16 + lr;
            int r1 = r0 + 8;
#pragma unroll
            for (int fn = 0; fn < 4; ++fn) {
                int cl = warp_n * 32 + fn * 8 + 2 * lc;
                float4 c = acc[fm][fn];
                if (plane == 0) {
                    if (r0 < M) *reinterpret_cast<float2*>(Cq + (size_t)r0 * 128 + cl) = make_float2(c.x, c.y);
                    if (r1 < M) *reinterpret_cast<float2*>(Cq + (size_t)r1 * 128 + cl) = make_float2(c.z, c.w);
                } else {
                    int hi = ((cl >> 2) << 3) + (cl & 3) + ((plane == 2) ? 4 : 0);
                    if (r0 < M) *reinterpret_cast<__half2*>(Hkv + (size_t)r0 * 256 + hi) = __floats2half2_rn(c.x, c.y);
                    if (r1 < M) *reinterpret_cast<__half2*>(Hkv + (size_t)r1 * 256 + hi) = __floats2half2_rn(c.z, c.w);
                }
            }
        }
        // no sync needed: epilogue touches only regs/global; Bs[0] reads finished
        // two chunk-syncs ago, so next plane's chunk-0 staging is safe.
    }
}

// ---------------- generic fp16 tensor-core GEMM (m16n8k16), N-tile=NT ----------
// EPI 1: bias + resid -> C (NCOLS=128)   EPI 2: bias + relu -> C (NCOLS=64)
template<int NT, int EPI>
__global__ __launch_bounds__(256)
void gemm_fp16(const float* __restrict__ A, const __half* __restrict__ BT,
               const float* __restrict__ bias, const float* __restrict__ resid,
               float* __restrict__ C, int M, int NCOLS)
{
    constexpr int WM = (NT == 128) ? 2 : 4;
    constexpr int WN = 8 / WM;
    constexpr int MFRAG = 8 / WM;
    constexpr int NFRAG = NT / (WN * 8);
    constexpr int PITCH = 24;

    __shared__ __half As[128][PITCH];
    __shared__ __half Bs[NT][PITCH];

    const int t = threadIdx.x;
    const int lane = t & 31;
    const int wid  = t >> 5;
    const int warp_m = wid / WN;
    const int warp_n = wid % WN;
    const int m0 = blockIdx.x * 128;
    const int n0 = blockIdx.y * NT;
    const int lr = lane >> 2, lc = lane & 3;

    float4 acc[MFRAG][NFRAG];
#pragma unroll
    for (int i = 0; i < MFRAG; ++i)
#pragma unroll
        for (int j = 0; j < NFRAG; ++j) acc[i][j] = make_float4(0.f, 0.f, 0.f, 0.f);

    const int arow = t >> 1;
    const int acb  = (t & 1) * 8;
    int agr = m0 + arow; if (agr >= M) agr = M - 1;
    const float* Ap = A + (size_t)agr * 128 + acb;

    const int brow = (NT == 128) ? (t >> 1) : (t >> 2);
    const int bcb  = (NT == 128) ? ((t & 1) * 8) : ((t & 3) * 4);
    const __half* Bp = BT + (size_t)(n0 + brow) * 128 + bcb;

    for (int k0 = 0; k0 < 128; k0 += 16) {
        float4 av0 = *reinterpret_cast<const float4*>(Ap + k0);
        float4 av1 = *reinterpret_cast<const float4*>(Ap + k0 + 4);
        __half2* asp = reinterpret_cast<__half2*>(&As[arow][acb]);
        asp[0] = __floats2half2_rn(av0.x, av0.y);
        asp[1] = __floats2half2_rn(av0.z, av0.w);
        asp[2] = __floats2half2_rn(av1.x, av1.y);
        asp[3] = __floats2half2_rn(av1.z, av1.w);
        if (NT == 128) {
            uint4 bv = *reinterpret_cast<const uint4*>(Bp + k0);
            uint32_t* bsp = reinterpret_cast<uint32_t*>(&Bs[brow][bcb]);
            bsp[0] = bv.x; bsp[1] = bv.y; bsp[2] = bv.z; bsp[3] = bv.w;
        } else {
            uint2 bv = *reinterpret_cast<const uint2*>(Bp + k0);
            uint32_t* bsp = reinterpret_cast<uint32_t*>(&Bs[brow][bcb]);
            bsp[0] = bv.x; bsp[1] = bv.y;
        }
        __syncthreads();

        uint32_t afr[MFRAG][4];
#pragma unroll
        for (int fm = 0; fm < MFRAG; ++fm) {
            int mr = warp_m * (MFRAG * 16) + fm * 16 + lr;
            afr[fm][0] = *reinterpret_cast<const uint32_t*>(&As[mr][2 * lc]);
            afr[fm][1] = *reinterpret_cast<const uint32_t*>(&As[mr + 8][2 * lc]);
            afr[fm][2] = *reinterpret_cast<const uint32_t*>(&As[mr][2 * lc + 8]);
            afr[fm][3] = *reinterpret_cast<const uint32_t*>(&As[mr + 8][2 * lc + 8]);
        }
        uint32_t bfr[NFRAG][2];
#pragma unroll
        for (int fn = 0; fn < NFRAG; ++fn) {
            int nc = warp_n * (NFRAG * 8) + fn * 8 + lr;
            bfr[fn][0] = *reinterpret_cast<const uint32_t*>(&Bs[nc][2 * lc]);
            bfr[fn][1] = *reinterpret_cast<const uint32_t*>(&Bs[nc][2 * lc + 8]);
        }
#pragma unroll
        for (int fm = 0; fm < MFRAG; ++fm)
#pragma unroll
            for (int fn = 0; fn < NFRAG; ++fn)
                mma_fp16(acc[fm][fn], afr[fm], bfr[fn]);
        __syncthreads();
    }

#pragma unroll
    for (int fm = 0; fm < MFRAG; ++fm) {
        int r0 = m0 + warp_m * (MFRAG * 16) + fm * 16 + lr;
        int r1 = r0 + 8;
#pragma unroll
        for (int fn = 0; fn < NFRAG; ++fn) {
            int cl = warp_n * (NFRAG * 8) + fn * 8 + 2 * lc;
            float4 c = acc[fm][fn];
            int col = n0 + cl;
            float b0 = bias[col], b1 = bias[col + 1];
            if (EPI == 1) {
                if (r0 < M) {
                    float2 rr = *reinterpret_cast<const float2*>(resid + (size_t)r0 * NCOLS + col);
                    *reinterpret_cast<float2*>(C + (size_t)r0 * NCOLS + col) =
                        make_float2(c.x + b0 + rr.x, c.y + b1 + rr.y);
                }
                if (r1 < M) {
                    float2 rr = *reinterpret_cast<const float2*>(resid + (size_t)r1 * NCOLS + col);
                    *reinterpret_cast<float2*>(C + (size_t)r1 * NCOLS + col) =
                        make_float2(c.z + b0 + rr.x, c.w + b1 + rr.y);
                }
            } else {
                if (r0 < M)
                    *reinterpret_cast<float2*>(C + (size_t)r0 * NCOLS + col) =
                        make_float2(fmaxf(c.x + b0, 0.f), fmaxf(c.y + b1, 0.f));
                if (r1 < M)
                    *reinterpret_cast<float2*>(C + (size_t)r1 * NCOLS + col) =
                        make_float2(fmaxf(c.z + b0, 0.f), fmaxf(c.w + b1, 0.f));
            }
        }
    }
}

// ---------------- fused CSR attention: 1 warp/node, EPW=8, ONE LDG.128 per edge ----------------
__global__ __launch_bounds__(128)
void fused_attn(const float* __restrict__ Wedge, int n)
{
    constexpr int EPW = 8;
    int i    = (blockIdx.x * blockDim.x + threadIdx.x) >> 5;
    int lane = threadIdx.x & 31;
    if (i >= n) return;
    int hg = lane >> 2;

    int beg = g_rowptr[i];
    int end = g_rowptr[i + 1];

    float4 q4 = *reinterpret_cast<const float4*>(g_q + (size_t)i * 128 + lane * 4);
    q4.x *= 0.25f; q4.y *= 0.25f; q4.z *= 0.25f; q4.w *= 0.25f;
    float w0 = Wedge[hg], w1 = Wedge[8 + hg];

    float4 accv = {0.f, 0.f, 0.f, 0.f};
    float  accd = 0.f;

    for (int j = beg; j < end; j += EPW) {
        int   idx[EPW];
        float sb[EPW];
#pragma unroll
        for (int u = 0; u < EPW; ++u) {
            int jj = min(j + u, end - 1);
            idx[u] = __ldg(g_esrc + jj);
            float2 ea2 = g_eea[jj];
            sb[u] = ea2.x * w0 + ea2.y * w1;
        }
        uint4 kv[EPW];
#pragma unroll
        for (int u = 0; u < EPW; ++u)
            kv[u] = *reinterpret_cast<const uint4*>(g_kv + (size_t)idx[u] * 256 + lane * 8);

        float ex[EPW];
#pragma unroll
        for (int u = 0; u < EPW; ++u) {
            float2 ka = __half22float2(*reinterpret_cast<const __half2*>(&kv[u].x));
            float2 kb = __half22float2(*reinterpret_cast<const __half2*>(&kv[u].y));
            float p = q4.x * ka.x + q4.y * ka.y + q4.z * kb.x + q4.w * kb.y;
            p += __shfl_xor_sync(0xffffffffu, p, 1);
            p += __shfl_xor_sync(0xffffffffu, p, 2);
            float e = __expf(p + sb[u]);
            ex[u] = (j + u < end) ? e : 0.f;
            accd += ex[u];
        }
#pragma unroll
        for (int u = 0; u < EPW; ++u) {
            float2 va = __half22float2(*reinterpret_cast<const __half2*>(&kv[u].z));
            float2 vb = __half22float2(*reinterpret_cast<const __half2*>(&kv[u].w));
            accv.x += ex[u] * va.x;
            accv.y += ex[u] * va.y;
            accv.z += ex[u] * vb.x;
            accv.w += ex[u] * vb.y;
        }
    }

    float invd = __fdividef(1.f, accd + 1e-16f);
    float4 o = {accv.x * invd, accv.y * invd, accv.z * invd, accv.w * invd};
    *reinterpret_cast<float4*>(g_agg + (size_t)i * 128 + lane * 4) = o;
}

// ---------------- layernorm ----------------
__global__ __launch_bounds__(256)
void ln_kernel(const float* __restrict__ lw, const float* __restrict__ lb, int n)
{
    int node = (blockIdx.x * blockDim.x + threadIdx.x) >> 5;
    int lane = threadIdx.x & 31;
    if (node >= n) return;

    float4 v = *reinterpret_cast<const float4*>(g_h + (size_t)node * 128 + lane * 4);
    float s = v.x + v.y + v.z + v.w;
    float q = v.x * v.x + v.y * v.y + v.z * v.z + v.w * v.w;
#pragma unroll
    for (int o = 16; o; o >>= 1) {
        s += __shfl_xor_sync(0xffffffffu, s, o);
        q += __shfl_xor_sync(0xffffffffu, q, o);
    }
    float mu  = s * (1.f / 128.f);
    float var = q * (1.f / 128.f) - mu * mu;
    float rs  = rsqrtf(var + 1e-5f);
    float4 w4 = *reinterpret_cast<const float4*>(lw + lane * 4);
    float4 b4 = *reinterpret_cast<const float4*>(lb + lane * 4);
    float4 o;
    o.x = (v.x - mu) * rs * w4.x + b4.x;
    o.y = (v.y - mu) * rs * w4.y + b4.y;
    o.z = (v.z - mu) * rs * w4.z + b4.z;
    o.w = (v.w - mu) * rs * w4.w + b4.w;
    *reinterpret_cast<float4*>(g_hn + (size_t)node * 128 + lane * 4) = o;
}

// ---------------- final: out[N,3] = t2[N,64] @ Wc2[64,3] + bc2 ----------------
__global__ __launch_bounds__(256)
void final_kernel(const float* __restrict__ Wc2, const float* __restrict__ bc2,
                  float* __restrict__ out, int n)
{
    int node = (blockIdx.x * blockDim.x + threadIdx.x) >> 5;
    int lane = threadIdx.x & 31;
    if (node >= n) return;

    float2 tv = *reinterpret_cast<const float2*>(g_t2 + (size_t)node * 64 + lane * 2);
    int k0 = lane * 2;
    float s0 = tv.x * Wc2[k0 * 3 + 0] + tv.y * Wc2[k0 * 3 + 3];
    float s1 = tv.x * Wc2[k0 * 3 + 1] + tv.y * Wc2[k0 * 3 + 4];
    float s2 = tv.x * Wc2[k0 * 3 + 2] + tv.y * Wc2[k0 * 3 + 5];
#pragma unroll
    for (int o = 16; o; o >>= 1) {
        s0 += __shfl_xor_sync(0xffffffffu, s0, o);
        s1 += __shfl_xor_sync(0xffffffffu, s1, o);
        s2 += __shfl_xor_sync(0xffffffffu, s2, o);
    }
    if (lane == 0) {
        out[(size_t)node * 3 + 0] = s0 + bc2[0];
        out[(size_t)node * 3 + 1] = s1 + bc2[1];
        out[(size_t)node * 3 + 2] = s2 + bc2[2];
    }
}

// ---------------- launch ----------------
extern "C" void kernel_launch(void* const* d_in, const int* in_sizes, int n_in,
                              void* d_out, int out_size)
{
    const float* x     = (const float*)d_in[0];
    const int*   ei    = (const int*)d_in[1];
    const float* ea    = (const float*)d_in[2];
    const float* Wqkv  = (const float*)d_in[3];
    const float* Wedge = (const float*)d_in[4];
    const float* Wout  = (const float*)d_in[5];
    const float* bout  = (const float*)d_in[6];
    const float* lnw   = (const float*)d_in[7];
    const float* lnb   = (const float*)d_in[8];
    const float* Wc1   = (const float*)d_in[9];
    const float* bc1   = (const float*)d_in[10];
    const float* Wc2   = (const float*)d_in[11];
    const float* bc2   = (const float*)d_in[12];
    float* out = (float*)d_out;

    const int n = in_sizes[0] / 128;
    const int E = in_sizes[1] / 2;
    const int nb = (n + 1023) >> 10;

    float *q, *agg, *h, *hn, *t2;
    __half *kv, *wqkvT, *woutT, *wc1T;
    cudaGetSymbolAddress((void**)&q,     g_q);
    cudaGetSymbolAddress((void**)&kv,    g_kv);
    cudaGetSymbolAddress((void**)&agg,   g_agg);
    cudaGetSymbolAddress((void**)&h,     g_h);
    cudaGetSymbolAddress((void**)&hn,    g_hn);
    cudaGetSymbolAddress((void**)&t2,    g_t2);
    cudaGetSymbolAddress((void**)&wqkvT, g_wqkvT);
    cudaGetSymbolAddress((void**)&woutT, g_woutT);
    cudaGetSymbolAddress((void**)&wc1T,  g_wc1T);

    // 1. edge histogram
    hist_kernel<<<(E + 255) / 256, 256>>>(ei, E, n);

    // 2. block sums for scan
    scan1_kernel<<<nb, 1024>>>(n);

    // 3. weight transpose+fp16 convert
    prep_kernel<<<(73728 + 255) / 256, 256>>>(Wqkv, Wout, Wc1);

    // 4. qkv (single pass over A, all 3 planes)   <-- profiled slot
    gemm_qkv<<<(n + 127) / 128, 256>>>(x, wqkvT, q, kv, n);

    // 5. finish scan -> rowptr/cursor
    scan2_kernel<<<nb, 1024>>>(n, nb);

    // 6. scatter edges into CSR (+ re-zero g_deg for next replay)
    scatter_kernel<<<(E + 255) / 256, 256>>>(ei, ea, E, n);

    // 7. fused per-node attention
    fused_attn<<<(n + 3) / 4, 128>>>(Wedge, n);

    // 8. h = agg @ Wout + bout + x
    gemm_fp16<128, 1><<<dim3((n + 127) / 128, 1), 256>>>(
        agg, woutT, bout, x, h, n, 128);

    // 9. layernorm
    ln_kernel<<<(n + 7) / 8, 256>>>(lnw, lnb, n);

    // 10. t2 = relu(hn @ Wc1 + bc1)
    gemm_fp16<64, 2><<<dim3((n + 127) / 128, 1), 256>>>(
        hn, wc1T, bc1, nullptr, t2, n, 64);

    // 11. out = t2 @ Wc2 + bc2
    final_kernel<<<(n + 7) / 8, 256>>>(Wc2, bc2, out, n);
}